// round 1
// baseline (speedup 1.0000x reference)
#include <cuda_runtime.h>
#include <math.h>

#define BATCH 16
#define NP    10000
#define NNB   10

// Scratch (allocation-free: __device__ globals)
__device__ __align__(16) float g_T[NP * BATCH * 9];     // [p][b][9]
__device__ __align__(16) float g_bvec[NP * BATCH * 3];  // [p][b*3+e]  = [p][48]

// ---------------------------------------------------------------------------
// Kernel 1: T[b,p] = R(f[:3]) @ S(f[3:9]); store as [p][b][9]
// ---------------------------------------------------------------------------
__global__ void ftoT_kernel(const float* __restrict__ geo) {
    int t = blockIdx.x * blockDim.x + threadIdx.x;
    if (t >= BATCH * NP) return;
    int bb = t / NP;       // batch
    int p  = t % NP;       // point (fastest -> coalesced reads)
    const float* f = geo + (size_t)(bb * NP + p) * 9;
    float x = f[0], y = f[1], z = f[2];
    float s3 = f[3], s4 = f[4], s5 = f[5], s6 = f[6], s7 = f[7], s8 = f[8];

    float th = sqrtf(x * x + y * y + z * z);
    float R00, R01, R02, R10, R11, R12, R20, R21, R22;
    if (th == 0.0f) {
        R00 = 1.0f; R01 = 0.0f; R02 = 0.0f;
        R10 = 0.0f; R11 = 1.0f; R12 = 0.0f;
        R20 = 0.0f; R21 = 0.0f; R22 = 1.0f;
    } else {
        float inv = 1.0f / th;
        float ka = x * inv, kb = y * inv, kc = z * inv;
        float st = sinf(th);
        float omc = 1.0f - cosf(th);
        // Kn = [[0,a,b],[-a,0,c],[-b,-c,0]], Kn^2 symmetric
        R00 = 1.0f - omc * (ka * ka + kb * kb);
        R01 =  st * ka - omc * kb * kc;
        R02 =  st * kb + omc * ka * kc;
        R10 = -st * ka - omc * kb * kc;
        R11 = 1.0f - omc * (ka * ka + kc * kc);
        R12 =  st * kc - omc * ka * kb;
        R20 = -st * kb + omc * ka * kc;
        R21 = -st * kc - omc * ka * kb;
        R22 = 1.0f - omc * (kb * kb + kc * kc);
    }
    // S = [[s3,s4,s5],[s4,s6,s7],[s5,s7,s8]],  T = R @ S
    float T0 = R00 * s3 + R01 * s4 + R02 * s5;
    float T1 = R00 * s4 + R01 * s6 + R02 * s7;
    float T2 = R00 * s5 + R01 * s7 + R02 * s8;
    float T3 = R10 * s3 + R11 * s4 + R12 * s5;
    float T4 = R10 * s4 + R11 * s6 + R12 * s7;
    float T5 = R10 * s5 + R11 * s7 + R12 * s8;
    float T6 = R20 * s3 + R21 * s4 + R22 * s5;
    float T7 = R20 * s4 + R21 * s6 + R22 * s7;
    float T8 = R20 * s5 + R21 * s7 + R22 * s8;

    float* o = g_T + ((size_t)p * BATCH + bb) * 9;
    o[0] = T0; o[1] = T1; o[2] = T2;
    o[3] = T3; o[4] = T4; o[5] = T5;
    o[6] = T6; o[7] = T7; o[8] = T8;
}

// ---------------------------------------------------------------------------
// Kernel 2: bvec[p][b] = T_own @ (sum_n v_n) + sum_n T_nb @ v_n
// thread = (p, b) with b in low 4 bits -> neighbor gathers contiguous per p
// ---------------------------------------------------------------------------
__global__ void bvec_kernel(const int* __restrict__ nb,
                            const float* __restrict__ vdiff) {
    int t = blockIdx.x * blockDim.x + threadIdx.x;
    int bb = t & (BATCH - 1);
    int p  = t >> 4;
    if (p >= NP) return;

    const float* Tp = g_T + ((size_t)p * BATCH + bb) * 9;
    float T0 = Tp[0], T1 = Tp[1], T2 = Tp[2];
    float T3 = Tp[3], T4 = Tp[4], T5 = Tp[5];
    float T6 = Tp[6], T7 = Tp[7], T8 = Tp[8];

    float a0 = 0.f, a1 = 0.f, a2 = 0.f;
    float v0s = 0.f, v1s = 0.f, v2s = 0.f;

#pragma unroll
    for (int n = 0; n < NNB; n++) {
        int idx = __ldg(nb + p * NNB + n);
        const float* vd = vdiff + ((size_t)p * NNB + n) * 3;
        float v0 = __ldg(vd + 0), v1 = __ldg(vd + 1), v2 = __ldg(vd + 2);
        v0s += v0; v1s += v1; v2s += v2;
        if (idx > 0) {
            const float* Tn = g_T + ((size_t)(idx - 1) * BATCH + bb) * 9;
            a0 += Tn[0] * v0 + Tn[1] * v1 + Tn[2] * v2;
            a1 += Tn[3] * v0 + Tn[4] * v1 + Tn[5] * v2;
            a2 += Tn[6] * v0 + Tn[7] * v1 + Tn[8] * v2;
        }
    }
    a0 += T0 * v0s + T1 * v1s + T2 * v2s;
    a1 += T3 * v0s + T4 * v1s + T5 * v2s;
    a2 += T6 * v0s + T7 * v1s + T8 * v2s;

    float* o = g_bvec + (size_t)p * (BATCH * 3) + bb * 3;
    o[0] = a0; o[1] = a1; o[2] = a2;
}

// ---------------------------------------------------------------------------
// Kernel 3: out[b,v,e] = sum_p recon[v,p] * bvec[p][b*3+e]
// SGEMM M=10000, N=48, K=10000. Split-K=5 with atomicAdd.
// ---------------------------------------------------------------------------
#define BM 128
#define BK 16
#define BN 48
#define KSPLIT 5
#define NTILES (NP / BK)   // 625

__global__ __launch_bounds__(128) void gemm_kernel(const float* __restrict__ A,
                                                   float* __restrict__ out) {
    __shared__ float As[BK][BM];   // transposed A tile
    __shared__ float Bs[BK][BN];

    int bx = blockIdx.x;
    int kz = blockIdx.y;
    int t  = threadIdx.x;
    int rg = t >> 3;   // 16 row groups of 8
    int cg = t & 7;    // 8 col groups of 6

    float acc[8][6];
#pragma unroll
    for (int i = 0; i < 8; i++)
#pragma unroll
        for (int j = 0; j < 6; j++) acc[i][j] = 0.f;

    int row0 = bx * BM;

    for (int tile = kz; tile < NTILES; tile += KSPLIT) {
        int k0 = tile * BK;
        // Load A tile: 128x16 floats = 512 float4 (coalesced along k)
#pragma unroll
        for (int i = 0; i < 4; i++) {
            int q  = i * 128 + t;
            int r  = q >> 2;
            int c4 = q & 3;
            int gr = row0 + r;
            float4 v = make_float4(0.f, 0.f, 0.f, 0.f);
            if (gr < NP)
                v = *(const float4*)(A + (size_t)gr * NP + k0 + c4 * 4);
            As[c4 * 4 + 0][r] = v.x;
            As[c4 * 4 + 1][r] = v.y;
            As[c4 * 4 + 2][r] = v.z;
            As[c4 * 4 + 3][r] = v.w;
        }
        // Load B tile: 16x48 floats = 192 float4
#pragma unroll
        for (int i = 0; i < 2; i++) {
            int q = i * 128 + t;
            if (q < 192) {
                int r  = q / 12;
                int c4 = q % 12;
                float4 v = *(const float4*)(g_bvec + (size_t)(k0 + r) * BN + c4 * 4);
                *(float4*)&Bs[r][c4 * 4] = v;
            }
        }
        __syncthreads();

#pragma unroll
        for (int k = 0; k < BK; k++) {
            float a[8], b[6];
#pragma unroll
            for (int i = 0; i < 8; i++) a[i] = As[k][rg * 8 + i];
#pragma unroll
            for (int j = 0; j < 6; j++) b[j] = Bs[k][cg * 6 + j];
#pragma unroll
            for (int i = 0; i < 8; i++)
#pragma unroll
                for (int j = 0; j < 6; j++) acc[i][j] += a[i] * b[j];
        }
        __syncthreads();
    }

    // Writeback: col c = b*3+e ; out[b][v][e]
#pragma unroll
    for (int i = 0; i < 8; i++) {
        int v = row0 + rg * 8 + i;
        if (v < NP) {
#pragma unroll
            for (int j = 0; j < 6; j++) {
                int c = cg * 6 + j;
                int bo = c / 3, e = c % 3;
                atomicAdd(out + ((size_t)bo * NP + v) * 3 + e, acc[i][j]);
            }
        }
    }
}

// ---------------------------------------------------------------------------
extern "C" void kernel_launch(void* const* d_in, const int* in_sizes, int n_in,
                              void* d_out, int out_size) {
    const float* geo   = (const float*)d_in[0];   // (16,10000,9)
    const int*   nb    = (const int*)d_in[1];     // (10000,10)
    const float* recon = (const float*)d_in[2];   // (10000,10000)
    const float* vdiff = (const float*)d_in[3];   // (10000,10,3)
    float* out = (float*)d_out;                   // (16,10000,3)

    ftoT_kernel<<<(BATCH * NP + 255) / 256, 256>>>(geo);
    bvec_kernel<<<(BATCH * NP + 255) / 256, 256>>>(nb, vdiff);
    cudaMemsetAsync(out, 0, (size_t)out_size * sizeof(float), 0);
    dim3 grid((NP + BM - 1) / BM, KSPLIT);
    gemm_kernel<<<grid, 128>>>(recon, out);
}

// round 3
// speedup vs baseline: 2.4097x; 2.4097x over previous
#include <cuda_runtime.h>
#include <cuda_bf16.h>
#include <math.h>
#include <stdint.h>

#define BATCH 16
#define NP    10000
#define NNB   10
#define NCOL  48
#define BPAD  10016          // padded K for B operand (multiple of 32)
#define BK    32
#define NKT   313            // ceil(10000/32)
#define KSPLIT 5
#define TPS   63             // k-tiles per split (ceil 313/5)
#define MT    128

// ---------------- scratch (__device__ globals; zero-init) ------------------
__device__ __align__(16) float g_T[NP * BATCH * 9];             // [p][b][9]
__device__ __align__(16) __nv_bfloat16 g_bh[NCOL * BPAD];       // B hi [c][k]
__device__ __align__(16) __nv_bfloat16 g_bl[NCOL * BPAD];       // B lo [c][k]

__device__ __forceinline__ uint32_t smem_u32(const void* p) {
    uint32_t a;
    asm("{ .reg .u64 t; cvta.to.shared.u64 t, %1; cvt.u32.u64 %0, t; }"
        : "=r"(a) : "l"(p));
    return a;
}

#define LDSM4(r0, r1, r2, r3, addr) \
    asm volatile("ldmatrix.sync.aligned.m8n8.x4.shared.b16 {%0,%1,%2,%3}, [%4];" \
                 : "=r"(r0), "=r"(r1), "=r"(r2), "=r"(r3) : "r"(addr))

#define MMA(d, a0, a1, a2, a3, b0, b1) \
    asm volatile("mma.sync.aligned.m16n8k16.row.col.f32.bf16.bf16.f32 " \
                 "{%0,%1,%2,%3}, {%4,%5,%6,%7}, {%8,%9}, {%0,%1,%2,%3};" \
                 : "+f"((d)[0]), "+f"((d)[1]), "+f"((d)[2]), "+f"((d)[3]) \
                 : "r"(a0), "r"(a1), "r"(a2), "r"(a3), "r"(b0), "r"(b1))

// ---------------------------------------------------------------------------
// Kernel 1: T[b,p] = R(f[:3]) @ S(f[3:9]); store as [p][b][9]
// ---------------------------------------------------------------------------
__global__ void ftoT_kernel(const float* __restrict__ geo) {
    int t = blockIdx.x * blockDim.x + threadIdx.x;
    if (t >= BATCH * NP) return;
    int bb = t / NP;
    int p  = t % NP;
    const float* f = geo + (size_t)(bb * NP + p) * 9;
    float x = f[0], y = f[1], z = f[2];
    float s3 = f[3], s4 = f[4], s5 = f[5], s6 = f[6], s7 = f[7], s8 = f[8];

    float th = sqrtf(x * x + y * y + z * z);
    float R00, R01, R02, R10, R11, R12, R20, R21, R22;
    if (th == 0.0f) {
        R00 = 1.f; R01 = 0.f; R02 = 0.f;
        R10 = 0.f; R11 = 1.f; R12 = 0.f;
        R20 = 0.f; R21 = 0.f; R22 = 1.f;
    } else {
        float inv = 1.0f / th;
        float ka = x * inv, kb = y * inv, kc = z * inv;
        float st = sinf(th);
        float omc = 1.0f - cosf(th);
        R00 = 1.0f - omc * (ka * ka + kb * kb);
        R01 =  st * ka - omc * kb * kc;
        R02 =  st * kb + omc * ka * kc;
        R10 = -st * ka - omc * kb * kc;
        R11 = 1.0f - omc * (ka * ka + kc * kc);
        R12 =  st * kc - omc * ka * kb;
        R20 = -st * kb + omc * ka * kc;
        R21 = -st * kc - omc * ka * kb;
        R22 = 1.0f - omc * (kb * kb + kc * kc);
    }
    float T0 = R00 * s3 + R01 * s4 + R02 * s5;
    float T1 = R00 * s4 + R01 * s6 + R02 * s7;
    float T2 = R00 * s5 + R01 * s7 + R02 * s8;
    float T3 = R10 * s3 + R11 * s4 + R12 * s5;
    float T4 = R10 * s4 + R11 * s6 + R12 * s7;
    float T5 = R10 * s5 + R11 * s7 + R12 * s8;
    float T6 = R20 * s3 + R21 * s4 + R22 * s5;
    float T7 = R20 * s4 + R21 * s6 + R22 * s7;
    float T8 = R20 * s5 + R21 * s7 + R22 * s8;

    float* o = g_T + ((size_t)p * BATCH + bb) * 9;
    o[0] = T0; o[1] = T1; o[2] = T2;
    o[3] = T3; o[4] = T4; o[5] = T5;
    o[6] = T6; o[7] = T7; o[8] = T8;
}

// ---------------------------------------------------------------------------
// Kernel 2: bvec -> transposed bf16 hi/lo:  g_b{h,l}[c][k], c = b*3+e
// ---------------------------------------------------------------------------
__global__ void bvec_kernel(const int* __restrict__ nb,
                            const float* __restrict__ vdiff) {
    int t = blockIdx.x * blockDim.x + threadIdx.x;
    int bb = t & (BATCH - 1);
    int p  = t >> 4;
    if (p >= NP) return;

    const float* Tp = g_T + ((size_t)p * BATCH + bb) * 9;
    float T0 = Tp[0], T1 = Tp[1], T2 = Tp[2];
    float T3 = Tp[3], T4 = Tp[4], T5 = Tp[5];
    float T6 = Tp[6], T7 = Tp[7], T8 = Tp[8];

    float a0 = 0.f, a1 = 0.f, a2 = 0.f;
    float v0s = 0.f, v1s = 0.f, v2s = 0.f;

#pragma unroll
    for (int n = 0; n < NNB; n++) {
        int idx = __ldg(nb + p * NNB + n);
        const float* vd = vdiff + ((size_t)p * NNB + n) * 3;
        float v0 = __ldg(vd + 0), v1 = __ldg(vd + 1), v2 = __ldg(vd + 2);
        v0s += v0; v1s += v1; v2s += v2;
        if (idx > 0) {
            const float* Tn = g_T + ((size_t)(idx - 1) * BATCH + bb) * 9;
            a0 += Tn[0] * v0 + Tn[1] * v1 + Tn[2] * v2;
            a1 += Tn[3] * v0 + Tn[4] * v1 + Tn[5] * v2;
            a2 += Tn[6] * v0 + Tn[7] * v1 + Tn[8] * v2;
        }
    }
    a0 += T0 * v0s + T1 * v1s + T2 * v2s;
    a1 += T3 * v0s + T4 * v1s + T5 * v2s;
    a2 += T6 * v0s + T7 * v1s + T8 * v2s;

    int c = bb * 3;
    float a[3] = {a0, a1, a2};
#pragma unroll
    for (int e = 0; e < 3; e++) {
        __nv_bfloat16 h = __float2bfloat16(a[e]);
        __nv_bfloat16 lo = __float2bfloat16(a[e] - __bfloat162float(h));
        g_bh[(size_t)(c + e) * BPAD + p] = h;
        g_bl[(size_t)(c + e) * BPAD + p] = lo;
    }
}

// ---------------------------------------------------------------------------
// Kernel 3: bf16 split GEMM via mma.sync.m16n8k16.
// out[b,v,e] = sum_p recon[v,p]*bvec[p][c];  M=10000,N=48,K=10000
// ---------------------------------------------------------------------------
#define SROW 40                       // smem row stride (bf16 elems)
#define OFF_AH 0
#define OFF_AL (128 * SROW)           // 5120
#define OFF_BH (2 * 128 * SROW)      // 10240
#define OFF_BL (OFF_BH + 48 * SROW)  // 12160
#define SM_ELEMS (OFF_BL + 48 * SROW)

__global__ __launch_bounds__(256, 3) void gemm_mma(const float* __restrict__ A,
                                                   float* __restrict__ out) {
    __shared__ __align__(16) __nv_bfloat16 sm[SM_ELEMS];

    const int t = threadIdx.x;
    const int w = t >> 5;
    const int l = t & 31;
    const int row0 = blockIdx.x * MT;

    const int mat = l >> 3, mrow = l & 7;
    const uint32_t smb = smem_u32(sm);

    // ldmatrix per-lane element offsets
    const int a_off = (w * 16 + ((mat & 1) << 3) + mrow) * SROW + ((mat >> 1) << 3);
    const int b_off = (((mat >> 1) << 3) + mrow) * SROW + ((mat & 1) << 3);

    float acc[6][4];
#pragma unroll
    for (int i = 0; i < 6; i++)
#pragma unroll
        for (int j = 0; j < 4; j++) acc[i][j] = 0.f;

    const int t0 = blockIdx.y * TPS;
    int t1 = t0 + TPS; if (t1 > NKT) t1 = NKT;
    const int nT = t1 - t0;

    // A-load mapping: 1024 float4 per tile; thread covers 4
    const int ar = t >> 3;           // base row pattern uses q = j*256+t
    const int ac = t & 7;

    float4 pa[4];
    uint4 pbh, pbl;
    const bool bldr = (t < 192);
    const int br = t >> 2, bseg = t & 3;

    // prefetch tile 0
    {
        int k0 = t0 * BK;
#pragma unroll
        for (int j = 0; j < 4; j++) {
            int q = j * 256 + t;
            int r = q >> 3, c = q & 7;
            int grow = row0 + r, gk = k0 + c * 4;
            float4 v = make_float4(0.f, 0.f, 0.f, 0.f);
            if (grow < NP && gk < NP)
                v = __ldg(reinterpret_cast<const float4*>(A + (size_t)grow * NP + gk));
            pa[j] = v;
        }
        if (bldr) {
            pbh = __ldg(reinterpret_cast<const uint4*>(g_bh + (size_t)br * BPAD + k0 + bseg * 8));
            pbl = __ldg(reinterpret_cast<const uint4*>(g_bl + (size_t)br * BPAD + k0 + bseg * 8));
        }
    }

    for (int i = 0; i < nT; i++) {
        // ---- STS current prefetched tile (fp32 -> bf16 hi/lo for A) -------
#pragma unroll
        for (int j = 0; j < 4; j++) {
            int q = j * 256 + t;
            int r = q >> 3, c = q & 7;
            float4 v = pa[j];
            __nv_bfloat16 h0 = __float2bfloat16(v.x);
            __nv_bfloat16 h1 = __float2bfloat16(v.y);
            __nv_bfloat16 h2 = __float2bfloat16(v.z);
            __nv_bfloat16 h3 = __float2bfloat16(v.w);
            __nv_bfloat16 l0 = __float2bfloat16(v.x - __bfloat162float(h0));
            __nv_bfloat16 l1 = __float2bfloat16(v.y - __bfloat162float(h1));
            __nv_bfloat16 l2 = __float2bfloat16(v.z - __bfloat162float(h2));
            __nv_bfloat16 l3 = __float2bfloat16(v.w - __bfloat162float(h3));
            int idx = r * SROW + c * 4;
            *reinterpret_cast<__nv_bfloat162*>(&sm[OFF_AH + idx])     = {h0, h1};
            *reinterpret_cast<__nv_bfloat162*>(&sm[OFF_AH + idx + 2]) = {h2, h3};
            *reinterpret_cast<__nv_bfloat162*>(&sm[OFF_AL + idx])     = {l0, l1};
            *reinterpret_cast<__nv_bfloat162*>(&sm[OFF_AL + idx + 2]) = {l2, l3};
        }
        if (bldr) {
            int idx = br * SROW + bseg * 8;
            *reinterpret_cast<uint4*>(&sm[OFF_BH + idx]) = pbh;
            *reinterpret_cast<uint4*>(&sm[OFF_BL + idx]) = pbl;
        }
        __syncthreads();

        // ---- prefetch next tile ------------------------------------------
        if (i + 1 < nT) {
            int k0 = (t0 + i + 1) * BK;
#pragma unroll
            for (int j = 0; j < 4; j++) {
                int q = j * 256 + t;
                int r = q >> 3, c = q & 7;
                int grow = row0 + r, gk = k0 + c * 4;
                float4 v = make_float4(0.f, 0.f, 0.f, 0.f);
                if (grow < NP && gk < NP)
                    v = __ldg(reinterpret_cast<const float4*>(A + (size_t)grow * NP + gk));
                pa[j] = v;
            }
            if (bldr) {
                pbh = __ldg(reinterpret_cast<const uint4*>(g_bh + (size_t)br * BPAD + k0 + bseg * 8));
                pbl = __ldg(reinterpret_cast<const uint4*>(g_bl + (size_t)br * BPAD + k0 + bseg * 8));
            }
        }

        // ---- compute ------------------------------------------------------
#pragma unroll
        for (int ks = 0; ks < 2; ks++) {
            int kk = ks * 16;
            uint32_t ah0, ah1, ah2, ah3, al0, al1, al2, al3;
            LDSM4(ah0, ah1, ah2, ah3, smb + (uint32_t)(OFF_AH + a_off + kk) * 2);
            LDSM4(al0, al1, al2, al3, smb + (uint32_t)(OFF_AL + a_off + kk) * 2);
#pragma unroll
            for (int ntp = 0; ntp < 3; ntp++) {
                uint32_t bh0, bh1, bh2, bh3, bl0, bl1, bl2, bl3;
                uint32_t boff = (uint32_t)(b_off + ntp * 16 * SROW + kk) * 2;
                LDSM4(bh0, bh1, bh2, bh3, smb + (uint32_t)OFF_BH * 2 + boff);
                LDSM4(bl0, bl1, bl2, bl3, smb + (uint32_t)OFF_BL * 2 + boff);
                MMA(acc[ntp * 2],     ah0, ah1, ah2, ah3, bh0, bh1);
                MMA(acc[ntp * 2],     ah0, ah1, ah2, ah3, bl0, bl1);
                MMA(acc[ntp * 2],     al0, al1, al2, al3, bh0, bh1);
                MMA(acc[ntp * 2 + 1], ah0, ah1, ah2, ah3, bh2, bh3);
                MMA(acc[ntp * 2 + 1], ah0, ah1, ah2, ah3, bl2, bl3);
                MMA(acc[ntp * 2 + 1], al0, al1, al2, al3, bh2, bh3);
            }
        }
        __syncthreads();
    }

    // ---- epilogue: atomicAdd into out[b][v][e] ---------------------------
    const int g = l >> 2, tg = l & 3;
    const int v0r = row0 + w * 16 + g;
#pragma unroll
    for (int nt = 0; nt < 6; nt++) {
        int c0 = nt * 8 + tg * 2;
#pragma unroll
        for (int half = 0; half < 2; half++) {
            int v = v0r + half * 8;
            if (v < NP) {
#pragma unroll
                for (int e2 = 0; e2 < 2; e2++) {
                    int c = c0 + e2;
                    int bo = c / 3, e = c - bo * 3;
                    atomicAdd(out + (size_t)bo * NP * 3 + (size_t)v * 3 + e,
                              acc[nt][half * 2 + e2]);
                }
            }
        }
    }
}

// ---------------------------------------------------------------------------
extern "C" void kernel_launch(void* const* d_in, const int* in_sizes, int n_in,
                              void* d_out, int out_size) {
    const float* geo   = (const float*)d_in[0];
    const int*   nb    = (const int*)d_in[1];
    const float* recon = (const float*)d_in[2];
    const float* vdiff = (const float*)d_in[3];
    float* out = (float*)d_out;

    ftoT_kernel<<<(BATCH * NP + 255) / 256, 256>>>(geo);
    bvec_kernel<<<(BATCH * NP + 255) / 256, 256>>>(nb, vdiff);
    cudaMemsetAsync(out, 0, (size_t)out_size * sizeof(float), 0);
    dim3 grid((NP + MT - 1) / MT, KSPLIT);
    gemm_mma<<<grid, 256>>>(recon, out);
}

// round 4
// speedup vs baseline: 3.5624x; 1.4784x over previous
#include <cuda_runtime.h>
#include <cuda_fp16.h>
#include <math.h>
#include <stdint.h>

#define BATCH 16
#define NP    10000
#define NNB   10
#define NCOL  48
#define BPAD  10016          // padded K for B operand (multiple of 32)
#define BK    32
#define NKT   313            // ceil(10000/32)
#define KSPLIT 5
#define TPS   63             // k-tiles per split
#define MT    128

// ---------------- scratch (__device__ globals; zero-init) ------------------
__device__ __align__(16) float g_T[NP * BATCH * 9];   // [p][b][9]
__device__ __align__(16) __half g_bh[NCOL * BPAD];    // B fp16 [c][k]

__device__ __forceinline__ uint32_t smem_u32(const void* p) {
    uint32_t a;
    asm("{ .reg .u64 t; cvta.to.shared.u64 t, %1; cvt.u32.u64 %0, t; }"
        : "=r"(a) : "l"(p));
    return a;
}

#define LDSM4(r0, r1, r2, r3, addr) \
    asm volatile("ldmatrix.sync.aligned.m8n8.x4.shared.b16 {%0,%1,%2,%3}, [%4];" \
                 : "=r"(r0), "=r"(r1), "=r"(r2), "=r"(r3) : "r"(addr))

#define MMA(d, a0, a1, a2, a3, b0, b1) \
    asm volatile("mma.sync.aligned.m16n8k16.row.col.f32.f16.f16.f32 " \
                 "{%0,%1,%2,%3}, {%4,%5,%6,%7}, {%8,%9}, {%0,%1,%2,%3};" \
                 : "+f"((d)[0]), "+f"((d)[1]), "+f"((d)[2]), "+f"((d)[3]) \
                 : "r"(a0), "r"(a1), "r"(a2), "r"(a3), "r"(b0), "r"(b1))

// ---------------------------------------------------------------------------
// Kernel 1: T[b,p] = R(f[:3]) @ S(f[3:9]); store as [p][b][9].
// Block = 16 b x 16 p; smem transpose so the global write is contiguous.
// ---------------------------------------------------------------------------
__global__ __launch_bounds__(256) void ftoT_kernel(const float* __restrict__ geo) {
    __shared__ float sT[16 * 145];   // [pi][145] padded rows

    const int tid = threadIdx.x;
    const int bb = tid >> 4;
    const int pi = tid & 15;
    const int p0 = blockIdx.x * 16;
    const int p  = p0 + pi;

    const float* f = geo + (size_t)(bb * NP + p) * 9;
    float x = f[0], y = f[1], z = f[2];
    float s3 = f[3], s4 = f[4], s5 = f[5], s6 = f[6], s7 = f[7], s8 = f[8];

    float th = sqrtf(x * x + y * y + z * z);
    float R00, R01, R02, R10, R11, R12, R20, R21, R22;
    if (th == 0.0f) {
        R00 = 1.f; R01 = 0.f; R02 = 0.f;
        R10 = 0.f; R11 = 1.f; R12 = 0.f;
        R20 = 0.f; R21 = 0.f; R22 = 1.f;
    } else {
        float inv = 1.0f / th;
        float ka = x * inv, kb = y * inv, kc = z * inv;
        float st = sinf(th);
        float omc = 1.0f - cosf(th);
        R00 = 1.0f - omc * (ka * ka + kb * kb);
        R01 =  st * ka - omc * kb * kc;
        R02 =  st * kb + omc * ka * kc;
        R10 = -st * ka - omc * kb * kc;
        R11 = 1.0f - omc * (ka * ka + kc * kc);
        R12 =  st * kc - omc * ka * kb;
        R20 = -st * kb + omc * ka * kc;
        R21 = -st * kc - omc * ka * kb;
        R22 = 1.0f - omc * (kb * kb + kc * kc);
    }
    float* o = sT + pi * 145 + bb * 9;
    o[0] = R00 * s3 + R01 * s4 + R02 * s5;
    o[1] = R00 * s4 + R01 * s6 + R02 * s7;
    o[2] = R00 * s5 + R01 * s7 + R02 * s8;
    o[3] = R10 * s3 + R11 * s4 + R12 * s5;
    o[4] = R10 * s4 + R11 * s6 + R12 * s7;
    o[5] = R10 * s5 + R11 * s7 + R12 * s8;
    o[6] = R20 * s3 + R21 * s4 + R22 * s5;
    o[7] = R20 * s4 + R21 * s6 + R22 * s7;
    o[8] = R20 * s5 + R21 * s7 + R22 * s8;
    __syncthreads();

    // contiguous write: 576 float4 (16 p x 144 floats)
    float4* dst = reinterpret_cast<float4*>(g_T + (size_t)p0 * 144);
#pragma unroll
    for (int q = tid; q < 576; q += 256) {
        int prow = q / 36;          // 36 float4 per p
        int s = q - prow * 36;
        const float* sp = sT + prow * 145 + s * 4;
        dst[q] = make_float4(sp[0], sp[1], sp[2], sp[3]);
    }
}

// ---------------------------------------------------------------------------
// Kernel 2: bvec -> transposed fp16:  g_bh[c][k], c = b*3+e
// ---------------------------------------------------------------------------
__global__ void bvec_kernel(const int* __restrict__ nb,
                            const float* __restrict__ vdiff) {
    int t = blockIdx.x * blockDim.x + threadIdx.x;
    int bb = t & (BATCH - 1);
    int p  = t >> 4;
    if (p >= NP) return;

    const float* Tp = g_T + ((size_t)p * BATCH + bb) * 9;
    float T0 = Tp[0], T1 = Tp[1], T2 = Tp[2];
    float T3 = Tp[3], T4 = Tp[4], T5 = Tp[5];
    float T6 = Tp[6], T7 = Tp[7], T8 = Tp[8];

    float a0 = 0.f, a1 = 0.f, a2 = 0.f;
    float v0s = 0.f, v1s = 0.f, v2s = 0.f;

#pragma unroll
    for (int n = 0; n < NNB; n++) {
        int idx = __ldg(nb + p * NNB + n);
        const float* vd = vdiff + ((size_t)p * NNB + n) * 3;
        float v0 = __ldg(vd + 0), v1 = __ldg(vd + 1), v2 = __ldg(vd + 2);
        v0s += v0; v1s += v1; v2s += v2;
        if (idx > 0) {
            const float* Tn = g_T + ((size_t)(idx - 1) * BATCH + bb) * 9;
            a0 += Tn[0] * v0 + Tn[1] * v1 + Tn[2] * v2;
            a1 += Tn[3] * v0 + Tn[4] * v1 + Tn[5] * v2;
            a2 += Tn[6] * v0 + Tn[7] * v1 + Tn[8] * v2;
        }
    }
    a0 += T0 * v0s + T1 * v1s + T2 * v2s;
    a1 += T3 * v0s + T4 * v1s + T5 * v2s;
    a2 += T6 * v0s + T7 * v1s + T8 * v2s;

    int c = bb * 3;
    g_bh[(size_t)(c + 0) * BPAD + p] = __float2half_rn(a0);
    g_bh[(size_t)(c + 1) * BPAD + p] = __float2half_rn(a1);
    g_bh[(size_t)(c + 2) * BPAD + p] = __float2half_rn(a2);
}

// ---------------------------------------------------------------------------
// Kernel 3: fp16 GEMM via mma.sync.m16n8k16. M=10000,N=48,K=10000, split-K=5.
// ---------------------------------------------------------------------------
#define SROW 40                      // smem row stride (fp16 elems)
#define OFF_AH 0
#define OFF_BH (128 * SROW)          // 5120
#define SM_ELEMS (OFF_BH + 48 * SROW)

__global__ __launch_bounds__(256, 3) void gemm_mma(const float* __restrict__ A,
                                                   float* __restrict__ out) {
    __shared__ __align__(16) __half sm[SM_ELEMS];

    const int t = threadIdx.x;
    const int w = t >> 5;
    const int l = t & 31;
    const int row0 = blockIdx.x * MT;

    const int mat = l >> 3, mrow = l & 7;
    const uint32_t smb = smem_u32(sm);

    const int a_off = (w * 16 + ((mat & 1) << 3) + mrow) * SROW + ((mat >> 1) << 3);
    const int b_off = (((mat >> 1) << 3) + mrow) * SROW + ((mat & 1) << 3);

    float acc[6][4];
#pragma unroll
    for (int i = 0; i < 6; i++)
#pragma unroll
        for (int j = 0; j < 4; j++) acc[i][j] = 0.f;

    const int t0 = blockIdx.y * TPS;
    int t1 = t0 + TPS; if (t1 > NKT) t1 = NKT;
    const int nT = t1 - t0;

    float4 pa[4];
    uint4 pbh;
    const bool bldr = (t < 192);
    const int br = t >> 2, bseg = t & 3;

    // prefetch tile 0
    {
        int k0 = t0 * BK;
#pragma unroll
        for (int j = 0; j < 4; j++) {
            int q = j * 256 + t;
            int r = q >> 3, c = q & 7;
            int grow = row0 + r, gk = k0 + c * 4;
            float4 v = make_float4(0.f, 0.f, 0.f, 0.f);
            if (grow < NP && gk < NP)
                v = __ldg(reinterpret_cast<const float4*>(A + (size_t)grow * NP + gk));
            pa[j] = v;
        }
        if (bldr)
            pbh = __ldg(reinterpret_cast<const uint4*>(g_bh + (size_t)br * BPAD + k0 + bseg * 8));
    }

    for (int i = 0; i < nT; i++) {
        // STS current tile (fp32 -> fp16 for A)
#pragma unroll
        for (int j = 0; j < 4; j++) {
            int q = j * 256 + t;
            int r = q >> 3, c = q & 7;
            float4 v = pa[j];
            __half2 h01 = __floats2half2_rn(v.x, v.y);
            __half2 h23 = __floats2half2_rn(v.z, v.w);
            int idx = r * SROW + c * 4;
            *reinterpret_cast<__half2*>(&sm[OFF_AH + idx])     = h01;
            *reinterpret_cast<__half2*>(&sm[OFF_AH + idx + 2]) = h23;
        }
        if (bldr)
            *reinterpret_cast<uint4*>(&sm[OFF_BH + br * SROW + bseg * 8]) = pbh;
        __syncthreads();

        // prefetch next tile
        if (i + 1 < nT) {
            int k0 = (t0 + i + 1) * BK;
#pragma unroll
            for (int j = 0; j < 4; j++) {
                int q = j * 256 + t;
                int r = q >> 3, c = q & 7;
                int grow = row0 + r, gk = k0 + c * 4;
                float4 v = make_float4(0.f, 0.f, 0.f, 0.f);
                if (grow < NP && gk < NP)
                    v = __ldg(reinterpret_cast<const float4*>(A + (size_t)grow * NP + gk));
                pa[j] = v;
            }
            if (bldr)
                pbh = __ldg(reinterpret_cast<const uint4*>(g_bh + (size_t)br * BPAD + k0 + bseg * 8));
        }

        // compute
#pragma unroll
        for (int ks = 0; ks < 2; ks++) {
            int kk = ks * 16;
            uint32_t a0, a1, a2, a3;
            LDSM4(a0, a1, a2, a3, smb + (uint32_t)(OFF_AH + a_off + kk) * 2);
#pragma unroll
            for (int ntp = 0; ntp < 3; ntp++) {
                uint32_t b0, b1, b2, b3;
                uint32_t boff = (uint32_t)(b_off + ntp * 16 * SROW + kk) * 2;
                LDSM4(b0, b1, b2, b3, smb + (uint32_t)OFF_BH * 2 + boff);
                MMA(acc[ntp * 2],     a0, a1, a2, a3, b0, b1);
                MMA(acc[ntp * 2 + 1], a0, a1, a2, a3, b2, b3);
            }
        }
        __syncthreads();
    }

    // epilogue: atomicAdd into out[b][v][e]
    const int g = l >> 2, tg = l & 3;
    const int v0r = row0 + w * 16 + g;
#pragma unroll
    for (int nt = 0; nt < 6; nt++) {
        int c0 = nt * 8 + tg * 2;
#pragma unroll
        for (int half = 0; half < 2; half++) {
            int v = v0r + half * 8;
            if (v < NP) {
#pragma unroll
                for (int e2 = 0; e2 < 2; e2++) {
                    int c = c0 + e2;
                    int bo = c / 3, e = c - bo * 3;
                    atomicAdd(out + (size_t)bo * NP * 3 + (size_t)v * 3 + e,
                              acc[nt][half * 2 + e2]);
                }
            }
        }
    }
}

// ---------------------------------------------------------------------------
extern "C" void kernel_launch(void* const* d_in, const int* in_sizes, int n_in,
                              void* d_out, int out_size) {
    const float* geo   = (const float*)d_in[0];
    const int*   nb    = (const int*)d_in[1];
    const float* recon = (const float*)d_in[2];
    const float* vdiff = (const float*)d_in[3];
    float* out = (float*)d_out;

    ftoT_kernel<<<NP / 16, 256>>>(geo);
    bvec_kernel<<<(BATCH * NP + 255) / 256, 256>>>(nb, vdiff);
    cudaMemsetAsync(out, 0, (size_t)out_size * sizeof(float), 0);
    dim3 grid((NP + MT - 1) / MT, KSPLIT);
    gemm_mma<<<grid, 256>>>(recon, out);
}